// round 17
// baseline (speedup 1.0000x reference)
#include <cuda_runtime.h>
#include <cuda_fp16.h>
#include <cstdint>
#include <cstddef>

// Problem constants
#define BB 4
#define SS 4096
#define HH 768
#define RR 242
#define HK 256
#define CP 256
#define RWIN 16      // g_e table size (prep computes 0..16)
#define MIXW 2       // mix window half-width: normalized w(d) < 1e-15 for d>=2
#define NFREQ 384

// ---------------- device scratch ---------------------------------------------------------
__device__ float g_T1t[RR * RR];
__device__ float g_e[RWIN + 1];
__device__ __align__(16) uint32_t g_vlh[CP * HH / 2];
__device__ __align__(16) uint32_t g_wch[HH * CP / 2];
__device__ __align__(16) uint32_t g_zf [(size_t)BB * SS * CP / 2];   // gemm1 out (slot space)

// ---------------- fp16 helpers -----------------------------------------------------------
__device__ __forceinline__ uint32_t pack_f16x2(float e0, float e1) {
    uint32_t r;
    asm("cvt.rn.f16x2.f32 %0, %1, %2;" : "=r"(r) : "f"(e1), "f"(e0));
    return r;
}
__device__ __forceinline__ void mma_f16(float* d, const uint32_t* a, uint32_t b0, uint32_t b1) {
    asm volatile(
        "mma.sync.aligned.m16n8k16.row.col.f32.f16.f16.f32 "
        "{%0,%1,%2,%3}, {%4,%5,%6,%7}, {%8,%9}, {%0,%1,%2,%3};"
        : "+f"(d[0]), "+f"(d[1]), "+f"(d[2]), "+f"(d[3])
        : "r"(a[0]), "r"(a[1]), "r"(a[2]), "r"(a[3]), "r"(b0), "r"(b1));
}
__device__ __forceinline__ uint32_t smem_u32(const void* p) {
    uint32_t a;
    asm("{ .reg .u64 t; cvta.to.shared.u64 t, %1; cvt.u32.u64 %0, t; }" : "=r"(a) : "l"(p));
    return a;
}
__device__ __forceinline__ void cp16(uint32_t dst, const void* src) {
    asm volatile("cp.async.cg.shared.global [%0], [%1], 16;" :: "r"(dst), "l"(src));
}
__device__ __forceinline__ void cp_commit() {
    asm volatile("cp.async.commit_group;" ::: "memory");
}
template<int N> __device__ __forceinline__ void cp_wait() {
    asm volatile("cp.async.wait_group %0;" :: "n"(N) : "memory");
}
__device__ __forceinline__ int pair_slot(int P) {
    return (P & 0x78) + 2 * (P & 3) + ((P >> 2) & 1);
}
__device__ __forceinline__ float2 h22f2(uint32_t v) {
    __half2 h = *reinterpret_cast<__half2*>(&v);
    return __half22float2(h);
}

// ---------------- pair-interleave conversion (hi only) -----------------------------------
__device__ __forceinline__ void conv_hi_idx(int idx, const float* __restrict__ src,
                                            int rows_src, int cols,
                                            uint32_t* __restrict__ hi) {
    int cols2 = cols >> 1;
    int row = idx / cols2;
    int s   = idx - row * cols2;
    int grp = s >> 3, j = s & 7;
    int k = (grp << 4) + (((j >> 1) + ((j & 1) << 2)) << 1);
    float e0 = 0.f, e1 = 0.f;
    if (row < rows_src) {
        e0 = src[(size_t)row * cols + k];
        e1 = src[(size_t)row * cols + k + 1];
    }
    hi[idx] = pack_f16x2(e0, e1);
}

// ---------------- 64x64 small gemm core --------------------------------------------------
#define WSM_BYTES (2 * 128 * 68 * 4)
template<bool PACKED>
__device__ void gemm64_body(float* smem,
                            const float* __restrict__ A, int lda,
                            const float* __restrict__ B, int ldb,
                            float* __restrict__ C, uint32_t* __restrict__ Cpk, int ldc,
                            int M, int N, int K, int m_t, int n_t) {
    float* As = smem;
    float* Bs = smem + 128 * 68;
    const int tid = threadIdx.x;
    const int m0 = m_t * 64, n0 = n_t * 64;
    const int ty = tid >> 4, tx = tid & 15;
    float acc[4][4] = {};
    for (int k0 = 0; k0 < K; k0 += 128) {
        const int kl = min(128, K - k0);
        #pragma unroll
        for (int i = 0; i < 32; i++) {
            int idx = tid + i * 256;
            int m = idx >> 7, k = idx & 127;
            float v = 0.f;
            if (k < kl && m0 + m < M) v = A[(size_t)(m0 + m) * lda + k0 + k];
            As[k * 68 + m] = v;
        }
        #pragma unroll
        for (int i = 0; i < 32; i++) {
            int idx = tid + i * 256;
            int k = idx >> 6, n = idx & 63;
            float v = 0.f;
            if (k < kl && n0 + n < N) v = B[(size_t)(k0 + k) * ldb + n0 + n];
            Bs[k * 68 + n] = v;
        }
        __syncthreads();
        for (int k = 0; k < kl; k++) {
            float4 a = *(const float4*)&As[k * 68 + ty * 4];
            float4 b = *(const float4*)&Bs[k * 68 + tx * 4];
            acc[0][0] += a.x * b.x; acc[0][1] += a.x * b.y; acc[0][2] += a.x * b.z; acc[0][3] += a.x * b.w;
            acc[1][0] += a.y * b.x; acc[1][1] += a.y * b.y; acc[1][2] += a.y * b.z; acc[1][3] += a.y * b.w;
            acc[2][0] += a.z * b.x; acc[2][1] += a.z * b.y; acc[2][2] += a.z * b.z; acc[2][3] += a.z * b.w;
            acc[3][0] += a.w * b.x; acc[3][1] += a.w * b.y; acc[3][2] += a.w * b.z; acc[3][3] += a.w * b.w;
        }
        __syncthreads();
    }
    #pragma unroll
    for (int i = 0; i < 4; i++) {
        int m = m0 + ty * 4 + i;
        if (m >= M) continue;
        if (PACKED) {
            #pragma unroll
            for (int j = 0; j < 4; j += 2) {
                int n = n0 + tx * 4 + j;
                int slot = pair_slot(n >> 1);
                Cpk[(size_t)m * (ldc >> 1) + slot] = pack_f16x2(acc[i][j], acc[i][j + 1]);
            }
        } else {
            #pragma unroll
            for (int j = 0; j < 4; j++) {
                int n = n0 + tx * 4 + j;
                if (n < N) C[(size_t)m * ldc + n] = acc[i][j];
            }
        }
    }
}

// ---------------- W1a: conv(v_low) + band-weight prep ------------------------------------
__global__ void __launch_bounds__(256)
wk1a(const float* __restrict__ v_low, uint32_t* __restrict__ vlh) {
    const int bid = blockIdx.x, tid = threadIdx.x;
    if (bid < 384) {
        conv_hi_idx(bid * 256 + tid, v_low, RR, HH, vlh);
    } else {
        int w = (bid - 384) * 8 + (tid >> 5);
        int lane = tid & 31;
        if (w > RWIN) return;
        float d = (float)w, s = 0.f;
        for (int j = lane; j < NFREQ; j += 32) {
            float f = expf(-(float)j * (9.210340371976184f / (float)NFREQ));
            s += cosf(d * f);
        }
        #pragma unroll
        for (int o = 16; o > 0; o >>= 1) s += __shfl_down_sync(0xffffffffu, s, o);
        if (lane == 0) g_e[w] = expf(s - (float)NFREQ);
    }
}

// ---------------- W1b / W2 (side stream) --------------------------------------------------
__global__ void __launch_bounds__(256)
wk1b(const float* __restrict__ o_low, const float* __restrict__ v_high,
     float* __restrict__ T1t) {
    extern __shared__ float wsm[];
    const int tb = blockIdx.x;
    gemm64_body<false>(wsm, o_low, HK, v_high, RR, T1t, nullptr, RR,
                       RR, RR, HK, tb >> 2, tb & 3);
}
__global__ void __launch_bounds__(256)
wk2(const float* __restrict__ o_high, const float* __restrict__ T1t,
    uint32_t* __restrict__ wch) {
    extern __shared__ float wsm[];
    const int cb = blockIdx.x;
    gemm64_body<true>(wsm, o_high, RR, T1t, RR, nullptr, wch, CP,
                      HH, RR, RR, cb >> 2, cb & 3);
}

// ---------------- gemm1: zf = round_f16(x @ v_low^T), slot-interleaved out ---------------
#define A_PITCH 72
#define B_PITCH 40
#define A_U32 (128 * A_PITCH)
#define B_U32 (128 * B_PITCH)
#define STAGE_U32 (A_U32 + B_U32)
#define SM_BYTES (2 * STAGE_U32 * 4)    // 114688 B

__global__ void __launch_bounds__(256, 2)
mma_gemm_abt(const float* __restrict__ A, int lda,
             const uint32_t* __restrict__ Bh, int ldbu,
             uint32_t* __restrict__ Cpk, int K) {
    extern __shared__ uint32_t sm4[];
    const uint32_t sb = smem_u32(sm4);
    const int tid  = threadIdx.x;
    const int wid  = tid >> 5;
    const int lane = tid & 31;
    const int m0 = blockIdx.y * 128;
    const int n0 = blockIdx.x * 128;
    const int mbw = (wid & 3) * 32;
    const int nbw = (wid >> 2) * 64;
    const int lr = lane >> 2;
    const int lc = lane & 3;

    const int ar = tid >> 4, ac = tid & 15;
    const int br = tid >> 3, bc = tid & 7;

    const float*    aSrc  = A  + (size_t)(m0 + ar) * lda + ac * 4;
    const uint32_t* bhSrc = Bh + (size_t)(n0 + br) * ldbu + bc * 4;
    const uint32_t aDst  = sb + (ar * A_PITCH + ac * 4) * 4;
    const uint32_t bhDst = sb + (A_U32 + br * B_PITCH + bc * 4) * 4;

    float acc[2][8][4] = {};
    const int nchunks = K >> 6;

    #define ISSUE(ch) do {                                                          \
        const uint32_t so_ = ((ch) & 1) * (STAGE_U32 * 4);                          \
        const int kf_ = (ch) << 6;                                                  \
        const int ku_ = (ch) << 5;                                                  \
        _Pragma("unroll")                                                           \
        for (int i_ = 0; i_ < 8; i_++)                                              \
            cp16(aDst + so_ + i_ * 16 * A_PITCH * 4,                                \
                 aSrc + kf_ + (size_t)i_ * 16 * lda);                               \
        _Pragma("unroll")                                                           \
        for (int i_ = 0; i_ < 4; i_++)                                              \
            cp16(bhDst + so_ + i_ * 32 * B_PITCH * 4,                               \
                 bhSrc + ku_ + (size_t)i_ * 32 * ldbu);                             \
        cp_commit();                                                                \
    } while (0)

    ISSUE(0);
    for (int ch = 0; ch < nchunks; ch++) {
        cp_wait<0>();
        __syncthreads();
        if (ch + 1 < nchunks) ISSUE(ch + 1);

        const uint32_t stg = (ch & 1) * STAGE_U32;
        const float* As = (const float*)(sm4 + stg);
        const uint32_t* BHs = sm4 + stg + A_U32;

        #pragma unroll
        for (int ks = 0; ks < 4; ks++) {
            uint32_t ah[2][4];
            #pragma unroll
            for (int t = 0; t < 2; t++) {
                const float* ap = As + (mbw + t * 16 + lr) * A_PITCH + ks * 16 + 2 * lc;
                float2 f0 = *(const float2*)(ap);
                float2 f1 = *(const float2*)(ap + 8 * A_PITCH);
                float2 f2 = *(const float2*)(ap + 8);
                float2 f3 = *(const float2*)(ap + 8 * A_PITCH + 8);
                ah[t][0] = pack_f16x2(f0.x, f0.y);
                ah[t][1] = pack_f16x2(f1.x, f1.y);
                ah[t][2] = pack_f16x2(f2.x, f2.y);
                ah[t][3] = pack_f16x2(f3.x, f3.y);
            }
            #pragma unroll
            for (int u = 0; u < 8; u++) {
                int rb = (nbw + u * 8 + lr) * B_PITCH + ks * 8 + 2 * lc;
                uint2 bh = *(const uint2*)(BHs + rb);
                #pragma unroll
                for (int t = 0; t < 2; t++)
                    mma_f16(acc[t][u], ah[t], bh.x, bh.y);
            }
        }
    }

    #pragma unroll
    for (int t = 0; t < 2; t++) {
        int row = m0 + mbw + t * 16 + lr;
        #pragma unroll
        for (int u = 0; u < 8; u++) {
            int col = n0 + nbw + u * 8 + lc * 2;
            int slot = pair_slot(col >> 1);
            Cpk[(size_t)row * 128 + slot]       = pack_f16x2(acc[t][u][0], acc[t][u][1]);
            Cpk[(size_t)(row + 8) * 128 + slot] = pack_f16x2(acc[t][u][2], acc[t][u][3]);
        }
    }
}

// ---------------- gemm2 (fused mix): out = mix(zf) @ Wc_f16^T, fp32 out ------------------
// Per chunk: stage 132 raw zf rows (halo 2 each side), smem mix -> mixed tile, MMA.
#define P2 40
#define RAWP 36                            // u32 pitch for raw tile (16B-aligned rows)
#define RAW_U32 (132 * RAWP)               // 4752
#define MIX_U32 (128 * P2)                 // 5120 (single-buffered)
#define B2_U32  (128 * P2)                 // 5120
#define SM2_BYTES ((2 * RAW_U32 + MIX_U32 + 2 * B2_U32) * 4)   // 99456 B

__global__ void __launch_bounds__(256, 2)
mma_gemm_fused(const uint32_t* __restrict__ zf,
               const uint32_t* __restrict__ Bh,
               float* __restrict__ C, int ldc) {
    extern __shared__ uint32_t sm4[];
    const uint32_t sb = smem_u32(sm4);
    __shared__ float swn[2 * MIXW + 1];    // normalized weights
    __shared__ float sws[2 * MIXW + 1];    // raw weights (boundary path)
    const int tid  = threadIdx.x;
    const int wid  = tid >> 5;
    const int lane = tid & 31;
    const int m0 = blockIdx.y * 128;
    const int n0 = blockIdx.x * 128;
    const int mbw = (wid & 3) * 32;
    const int nbw = (wid >> 2) * 64;
    const int lr = lane >> 2;
    const int lc = lane & 3;
    const int s0 = m0 & (SS - 1);
    const bool interior = (s0 != 0) && (s0 != SS - 128);

    if (tid < 2 * MIXW + 1) {
        float w = g_e[tid < MIXW ? MIXW - tid : tid - MIXW];
        sws[tid] = w;
        float Z = g_e[0];
        #pragma unroll
        for (int d = 1; d <= MIXW; d++) Z += 2.f * g_e[d];
        swn[tid] = w / Z;
    }

    // fill indices
    const int fr = tid >> 3, fc = tid & 7;         // B: rows fr+32i, 16B chunk fc
    const uint32_t* bSrc = Bh + (size_t)(n0 + fr) * 128 + fc * 4;

    float acc[2][8][4] = {};

    #define ISSUE2(ch) do {                                                         \
        const uint32_t soR = ((ch) & 1) * (RAW_U32 * 4);                            \
        const uint32_t soB = (2 * RAW_U32 + MIX_U32 + ((ch) & 1) * B2_U32) * 4;     \
        const int ku_ = (ch) << 5;                                                  \
        _Pragma("unroll")                                                           \
        for (int i_ = 0; i_ < 5; i_++) {                                            \
            int idx_ = tid + i_ * 256;                                              \
            if (idx_ < 1056) {                                                      \
                int r_ = idx_ >> 3, c_ = idx_ & 7;                                  \
                int gm_ = m0 - MIXW + r_;                                           \
                if (gm_ < 0) gm_ = 0;                                               \
                if (gm_ > BB * SS - 1) gm_ = BB * SS - 1;                           \
                cp16(sb + soR + (r_ * RAWP + c_ * 4) * 4,                           \
                     zf + (size_t)gm_ * 128 + ku_ + c_ * 4);                        \
            }                                                                       \
        }                                                                           \
        _Pragma("unroll")                                                           \
        for (int i_ = 0; i_ < 4; i_++)                                              \
            cp16(sb + soB + ((fr + 32 * i_) * P2 + fc * 4) * 4,                     \
                 bSrc + ku_ + (size_t)i_ * 32 * 128);                               \
        cp_commit();                                                                \
    } while (0)

    ISSUE2(0);
    for (int ch = 0; ch < 4; ch++) {
        cp_wait<0>();
        __syncthreads();
        if (ch + 1 < 4) ISSUE2(ch + 1);

        const uint32_t* raw = sm4 + (ch & 1) * RAW_U32;
        uint32_t* mixed = sm4 + 2 * RAW_U32;
        const uint32_t* BHs = sm4 + 2 * RAW_U32 + MIX_U32 + (ch & 1) * B2_U32;

        // ---- mix phase: raw (132 x 32) -> mixed (128 x 32), per-slot 5-tap ----
        {
            const int pr = tid & 31;
            const int r0 = (tid >> 5) * 16;
            if (interior) {
                float w2n = swn[0], w1n = swn[1], w0n = swn[2];
                float2 wv[5];
                #pragma unroll
                for (int j = 0; j < 4; j++)
                    wv[j] = h22f2(raw[(r0 + j) * RAWP + pr]);
                #pragma unroll
                for (int i = 0; i < 16; i++) {
                    wv[(i + 4) % 5] = h22f2(raw[(r0 + i + 4) * RAWP + pr]);
                    float2 v0 = wv[i % 5], v1 = wv[(i + 1) % 5], v2 = wv[(i + 2) % 5];
                    float2 v3 = wv[(i + 3) % 5], v4 = wv[(i + 4) % 5];
                    float a0 = w2n * (v0.x + v4.x) + w1n * (v1.x + v3.x) + w0n * v2.x;
                    float a1 = w2n * (v0.y + v4.y) + w1n * (v1.y + v3.y) + w0n * v2.y;
                    mixed[(r0 + i) * P2 + pr] = pack_f16x2(a0, a1);
                }
            } else {
                #pragma unroll
                for (int i = 0; i < 16; i++) {
                    int s = s0 + r0 + i;
                    float Z = 0.f, a0 = 0.f, a1 = 0.f;
                    #pragma unroll
                    for (int d = -MIXW; d <= MIXW; ++d) {
                        int t = s - d;
                        if ((unsigned)t < (unsigned)SS) {
                            float w = sws[d + MIXW];
                            Z += w;
                            float2 v = h22f2(raw[(r0 + i + MIXW - d) * RAWP + pr]);
                            a0 += w * v.x;
                            a1 += w * v.y;
                        }
                    }
                    float inv = 1.f / Z;
                    mixed[(r0 + i) * P2 + pr] = pack_f16x2(a0 * inv, a1 * inv);
                }
            }
        }
        __syncthreads();

        // ---- MMA phase ----
        #pragma unroll
        for (int ks = 0; ks < 4; ks++) {
            uint32_t ah[2][4];
            #pragma unroll
            for (int t = 0; t < 2; t++) {
                int ba = (mbw + t * 16 + lr) * P2 + ks * 8 + 2 * lc;
                uint2 h0 = *(const uint2*)(mixed + ba);
                uint2 h8 = *(const uint2*)(mixed + ba + 8 * P2);
                ah[t][0] = h0.x; ah[t][1] = h8.x; ah[t][2] = h0.y; ah[t][3] = h8.y;
            }
            #pragma unroll
            for (int u = 0; u < 8; u++) {
                int rb = (nbw + u * 8 + lr) * P2 + ks * 8 + 2 * lc;
                uint2 bh = *(const uint2*)(BHs + rb);
                #pragma unroll
                for (int t = 0; t < 2; t++)
                    mma_f16(acc[t][u], ah[t], bh.x, bh.y);
            }
        }
    }

    #pragma unroll
    for (int t = 0; t < 2; t++) {
        int row = m0 + mbw + t * 16 + lr;
        #pragma unroll
        for (int u = 0; u < 8; u++) {
            int col = n0 + nbw + u * 8 + lc * 2;
            *(float2*)(C + (size_t)row * ldc + col) = make_float2(acc[t][u][0], acc[t][u][1]);
            *(float2*)(C + (size_t)(row + 8) * ldc + col) = make_float2(acc[t][u][2], acc[t][u][3]);
        }
    }
}

// ---------------- launch ------------------------------------------------------------------
extern "C" void kernel_launch(void* const* d_in, const int* in_sizes, int n_in,
                              void* d_out, int out_size) {
    const float* x      = (const float*)d_in[0];
    const float* v_low  = (const float*)d_in[5];   // [242, 768]
    const float* v_high = (const float*)d_in[6];   // [256, 242]
    const float* o_low  = (const float*)d_in[7];   // [242, 256]
    const float* o_high = (const float*)d_in[8];   // [768, 242]
    float* out = (float*)d_out;                    // [4, 4096, 768]

    float* T1t = nullptr; cudaGetSymbolAddress((void**)&T1t, g_T1t);
    uint32_t* vlh = nullptr; cudaGetSymbolAddress((void**)&vlh, g_vlh);
    uint32_t* wch = nullptr; cudaGetSymbolAddress((void**)&wch, g_wch);
    uint32_t* zf  = nullptr; cudaGetSymbolAddress((void**)&zf,  g_zf);

    cudaFuncSetAttribute(mma_gemm_abt,   cudaFuncAttributeMaxDynamicSharedMemorySize, SM_BYTES);
    cudaFuncSetAttribute(mma_gemm_fused, cudaFuncAttributeMaxDynamicSharedMemorySize, SM2_BYTES);
    cudaFuncSetAttribute(wk1b, cudaFuncAttributeMaxDynamicSharedMemorySize, WSM_BYTES);
    cudaFuncSetAttribute(wk2,  cudaFuncAttributeMaxDynamicSharedMemorySize, WSM_BYTES);

    // one-time stream/event setup
    static cudaStream_t s2 = nullptr;
    static cudaEvent_t ev_fork = nullptr, ev_join = nullptr;
    if (s2 == nullptr) {
        cudaStreamCreateWithFlags(&s2, cudaStreamNonBlocking);
        cudaEventCreateWithFlags(&ev_fork, cudaEventDisableTiming);
        cudaEventCreateWithFlags(&ev_join, cudaEventDisableTiming);
    }

    // fork: weight branch on side stream
    cudaEventRecord(ev_fork, 0);
    cudaStreamWaitEvent(s2, ev_fork, 0);
    wk1b<<<16, 256, WSM_BYTES, s2>>>(o_low, v_high, T1t);
    wk2 <<<48, 256, WSM_BYTES, s2>>>(o_high, T1t, wch);
    cudaEventRecord(ev_join, s2);

    // main branch: conv(v_low)+prep -> gemm1
    wk1a<<<387, 256>>>(v_low, vlh);
    mma_gemm_abt<<<dim3(CP / 128, (BB * SS) / 128), 256, SM_BYTES>>>(
        x, HH, vlh, HH / 2, zf, HH);

    // join: fused mix+gemm2 needs wch
    cudaStreamWaitEvent(0, ev_join, 0);
    mma_gemm_fused<<<dim3(HH / 128, (BB * SS) / 128), 256, SM2_BYTES>>>(
        zf, wch, out, HH);

    (void)in_sizes; (void)n_in; (void)out_size;
}